// round 8
// baseline (speedup 1.0000x reference)
#include <cuda_runtime.h>
#include <cstdint>

// Problem constants
#define NB   32
#define LQ   2048
#define LK   2048
#define DIN  32
#define DKQ  20
#define EPS  1e-5f
// fold 1/sqrt(20) * log2(e) into q so scores are in log2 domain
#define QSCALE 0.32258572299984063f   // log2(e)/sqrt(20)

#define KSTRIDE 28   // padded K feature stride
#define QSTRIDE 24   // padded Q feature stride (3 k8 chunks)
#define VSTRIDE 36   // padded V stride

// Scratch (allocation-free rule: __device__ globals)
__device__ float d_vproj[(size_t)NB * LK * VSTRIDE];
__device__ float d_kproj[(size_t)NB * LK * KSTRIDE];
__device__ float d_qproj[(size_t)NB * LQ * QSTRIDE];

typedef unsigned int u32;

__device__ __forceinline__ float tf32r(float x) {
    u32 u; asm("cvt.rna.tf32.f32 %0, %1;" : "=r"(u) : "f"(x));
    return __uint_as_float(u);
}
__device__ __forceinline__ float ex2f(float x) {
    float r; asm("ex2.approx.f32 %0, %1;" : "=f"(r) : "f"(x));
    return r;
}
// m16n8k8 tf32 mma: D = A*B + C  (fp32 accum)
__device__ __forceinline__ void mma_tf32(
    float& d0, float& d1, float& d2, float& d3,
    u32 a0, u32 a1, u32 a2, u32 a3, u32 b0, u32 b1,
    float c0, float c1, float c2, float c3)
{
    asm("mma.sync.aligned.m16n8k8.row.col.f32.tf32.tf32.f32 "
        "{%0,%1,%2,%3},{%4,%5,%6,%7},{%8,%9},{%10,%11,%12,%13};"
        : "=f"(d0), "=f"(d1), "=f"(d2), "=f"(d3)
        : "r"(a0), "r"(a1), "r"(a2), "r"(a3), "r"(b0), "r"(b1),
          "f"(c0), "f"(c1), "f"(c2), "f"(c3));
}
__device__ __forceinline__ void cp16(u32 dst, const void* src) {
    asm volatile("cp.async.cg.shared.global [%0], [%1], 16;" :: "r"(dst), "l"(src));
}
#define CP_COMMIT() asm volatile("cp.async.commit_group;")
#define CP_WAIT0()  asm volatile("cp.async.wait_group 0;")

// ---------------------------------------------------------------------------
// Kernel 1: projections, split 3 ways by blockIdx.y (0=V, 1=K, 2=Q).
// ---------------------------------------------------------------------------
__global__ __launch_bounds__(256) void proj_kernel(
    const float* __restrict__ vals, const float* __restrict__ keys,
    const float* __restrict__ ques,
    const float* __restrict__ Wv, const float* __restrict__ Wk, const float* __restrict__ Wq,
    const float* __restrict__ gk, const float* __restrict__ bk,
    const float* __restrict__ gq, const float* __restrict__ bq)
{
    __shared__ float sW[DIN * DIN];
    __shared__ float sg[DKQ], sb[DKQ];

    int tid  = threadIdx.x;
    int task = blockIdx.y;
    size_t r = (size_t)blockIdx.x * 256 + tid;

    if (task == 0) {
        for (int i = tid; i < DIN * DIN; i += 256) sW[i] = Wv[i];
        __syncthreads();

        float x[DIN];
        const float4* p4 = (const float4*)(vals + r * DIN);
        #pragma unroll
        for (int i = 0; i < 8; i++) {
            float4 t = p4[i];
            x[4*i] = t.x; x[4*i+1] = t.y; x[4*i+2] = t.z; x[4*i+3] = t.w;
        }
        float outr[DIN];
        #pragma unroll
        for (int o = 0; o < DIN; o++) {
            float acc = 0.f;
            #pragma unroll
            for (int d = 0; d < DIN; d++) acc += x[d] * sW[o * DIN + d];
            outr[o] = tf32r(acc);
        }
        float4* o4 = (float4*)(d_vproj + r * VSTRIDE);
        #pragma unroll
        for (int i = 0; i < 8; i++)
            o4[i] = make_float4(outr[4*i], outr[4*i+1], outr[4*i+2], outr[4*i+3]);
        o4[8] = make_float4(0.f, 0.f, 0.f, 0.f);
    } else {
        const float* W  = (task == 1) ? Wk : Wq;
        const float* gg = (task == 1) ? gk : gq;
        const float* bb = (task == 1) ? bk : bq;
        const float* in = (task == 1) ? keys : ques;
        for (int i = tid; i < DKQ * DIN; i += 256) sW[i] = W[i];
        if (tid < DKQ) { sg[tid] = gg[tid]; sb[tid] = bb[tid]; }
        __syncthreads();

        float x[DIN];
        const float4* p4 = (const float4*)(in + r * DIN);
        #pragma unroll
        for (int i = 0; i < 8; i++) {
            float4 t = p4[i];
            x[4*i] = t.x; x[4*i+1] = t.y; x[4*i+2] = t.z; x[4*i+3] = t.w;
        }
        float y[DKQ];
        #pragma unroll
        for (int o = 0; o < DKQ; o++) {
            float acc = 0.f;
            #pragma unroll
            for (int d = 0; d < DIN; d++) acc += x[d] * sW[o * DIN + d];
            y[o] = acc;
        }
        float m = 0.f;
        #pragma unroll
        for (int c = 0; c < DKQ; c++) m += y[c];
        m *= (1.f / DKQ);
        float v = 0.f;
        #pragma unroll
        for (int c = 0; c < DKQ; c++) { float d = y[c] - m; v += d * d; }
        v *= (1.f / DKQ);
        float rs = rsqrtf(v + EPS);

        if (task == 1) {
            #pragma unroll
            for (int c = 0; c < DKQ; c++) y[c] = tf32r((y[c] - m) * rs * sg[c] + sb[c]);
            float4* o4 = (float4*)(d_kproj + r * KSTRIDE);
            #pragma unroll
            for (int i = 0; i < 5; i++)
                o4[i] = make_float4(y[4*i], y[4*i+1], y[4*i+2], y[4*i+3]);
            o4[5] = make_float4(0.f, 0.f, 0.f, 0.f);
            o4[6] = make_float4(0.f, 0.f, 0.f, 0.f);
        } else {
            #pragma unroll
            for (int c = 0; c < DKQ; c++)
                y[c] = tf32r(((y[c] - m) * rs * sg[c] + sb[c]) * QSCALE);
            float4* o4 = (float4*)(d_qproj + r * QSTRIDE);
            #pragma unroll
            for (int i = 0; i < 5; i++)
                o4[i] = make_float4(y[4*i], y[4*i+1], y[4*i+2], y[4*i+3]);
            o4[5] = make_float4(0.f, 0.f, 0.f, 0.f);
        }
    }
}

// ---------------------------------------------------------------------------
// Kernel 2: flash attention, mma.sync m16n8k8 tf32, cp.async double-buffered
// TS=64 K/V tiles, 2-stage software-pipelined chunk loop:
// QK MMAs of chunk j+1 are issued BEFORE exp/PV of chunk j, so tensor work
// overlaps the MUFU chain. CTA = 128 thr = 4 warps; warp: 32 queries.
// ---------------------------------------------------------------------------
#define TS 64
#define NT (LK / TS)
#define NC (TS / 8)               // chunks per tile
#define K4  (TS * KSTRIDE / 4)    // 448 float4 per K tile
#define V4  (TS * VSTRIDE / 4)    // 576 float4 per V tile

__global__ __launch_bounds__(128) void attn_kernel(
    const void* __restrict__ mask_raw, const float* __restrict__ ques,
    const float* __restrict__ go, const float* __restrict__ bo,
    float* __restrict__ out)
{
    __shared__ float sK[2][TS * KSTRIDE];
    __shared__ float sV[2][TS * VSTRIDE];
    __shared__ float sbias[2][TS];
    __shared__ int s_is_byte;

    int tid  = threadIdx.x;
    int w    = tid >> 5;
    int lane = tid & 31;
    int g    = lane >> 2;   // group id (0..7)
    int i    = lane & 3;    // thread in group (0..3)
    int b    = blockIdx.y;
    int qbase = blockIdx.x * 128 + w * 32;

    if (tid == 0) {
        // Detect mask storage: numpy bool (1 byte) vs int32 coercion.
        const unsigned int* wd = (const unsigned int*)mask_raw;
        unsigned int acc = 0;
        for (int k = 0; k < 64; k++) acc |= wd[k] & 0xFFFFFF00u;
        s_is_byte = (acc != 0u);
    }

    // ---- Q fragments: two m16 tiles, held in registers ----
    u32 aq[2][3][4];
    #pragma unroll
    for (int t = 0; t < 2; t++) {
        const float* q0p = d_qproj + ((size_t)b * LQ + qbase + t * 16 + g) * QSTRIDE;
        const float* q1p = q0p + 8 * QSTRIDE;
        #pragma unroll
        for (int c = 0; c < 3; c++) {
            aq[t][c][0] = __float_as_uint(q0p[c * 8 + i]);
            aq[t][c][1] = __float_as_uint(q1p[c * 8 + i]);
            aq[t][c][2] = __float_as_uint(q0p[c * 8 + i + 4]);
            aq[t][c][3] = __float_as_uint(q1p[c * 8 + i + 4]);
        }
    }

    float o[2][4][4];
    #pragma unroll
    for (int t = 0; t < 2; t++)
        #pragma unroll
        for (int nt = 0; nt < 4; nt++)
            #pragma unroll
            for (int r = 0; r < 4; r++) o[t][nt][r] = 0.f;
    float lac[2][2];
    lac[0][0] = lac[0][1] = lac[1][0] = lac[1][1] = 0.f;

    // pipeline stage state: scores of chunk in flight
    float s[2][2][4];          // [stage][mtile][reg]

    const float* kbase = d_kproj + (size_t)b * LK * KSTRIDE;
    const float* vbase = d_vproj + (size_t)b * LK * VSTRIDE;
    const unsigned char* mB = (const unsigned char*)mask_raw + (size_t)b * LK;
    const int*           mI = (const int*)mask_raw + (size_t)b * LK;

    __syncthreads();   // s_is_byte visible
    int is_byte = s_is_byte;

    // ---- preamble: async load tile 0, bias 0 ----
    {
        u32 k_u = (u32)__cvta_generic_to_shared(&sK[0][0]);
        u32 v_u = (u32)__cvta_generic_to_shared(&sV[0][0]);
        #pragma unroll
        for (int rr = 0; rr < 4; rr++) {
            int idx = tid + rr * 128;
            if (idx < K4) cp16(k_u + idx * 16, kbase + idx * 4);
        }
        #pragma unroll
        for (int rr = 0; rr < 5; rr++) {
            int idx = tid + rr * 128;
            if (idx < V4) cp16(v_u + idx * 16, vbase + idx * 4);
        }
        CP_COMMIT();
        if (tid < TS) {
            int mv = is_byte ? (int)mB[tid] : mI[tid];
            sbias[0][tid] = mv ? -1e30f : 0.f;   // True masks OUT
        }
    }

    for (int t0 = 0; t0 < NT; t0++) {
        int cur = t0 & 1;
        CP_WAIT0();
        __syncthreads();   // tile t0 ready; all warps done with buffer we refill

        // prefetch tile t0+1 (overlaps with compute below)
        if (t0 + 1 < NT) {
            int nxt = cur ^ 1;
            u32 k_u = (u32)__cvta_generic_to_shared(&sK[nxt][0]);
            u32 v_u = (u32)__cvta_generic_to_shared(&sV[nxt][0]);
            const float* kg = kbase + (size_t)(t0 + 1) * TS * KSTRIDE;
            const float* vg = vbase + (size_t)(t0 + 1) * TS * VSTRIDE;
            #pragma unroll
            for (int rr = 0; rr < 4; rr++) {
                int idx = tid + rr * 128;
                if (idx < K4) cp16(k_u + idx * 16, kg + idx * 4);
            }
            #pragma unroll
            for (int rr = 0; rr < 5; rr++) {
                int idx = tid + rr * 128;
                if (idx < V4) cp16(v_u + idx * 16, vg + idx * 4);
            }
            CP_COMMIT();
            if (tid < TS) {
                int mloc = (t0 + 1) * TS + tid;
                int mvn = is_byte ? (int)mB[mloc] : mI[mloc];
                sbias[nxt][tid] = mvn ? -1e30f : 0.f;
            }
        }

        // ---- helper to issue QK MMAs for chunk kc into stage st ----
        auto qk_stage = [&](int st, int kc) {
            float ba = sbias[cur][kc * 8 + 2 * i];
            float bb = sbias[cur][kc * 8 + 2 * i + 1];
            const float* kr = sK[cur] + (kc * 8 + g) * KSTRIDE;
            u32 kb[3][2];
            #pragma unroll
            for (int c = 0; c < 3; c++) {
                kb[c][0] = __float_as_uint(kr[c * 8 + i]);
                kb[c][1] = __float_as_uint(kr[c * 8 + i + 4]);
            }
            #pragma unroll
            for (int t = 0; t < 2; t++) {
                float s0 = ba, s1 = bb, s2 = ba, s3 = bb;
                #pragma unroll
                for (int c = 0; c < 3; c++) {
                    mma_tf32(s0, s1, s2, s3,
                             aq[t][c][0], aq[t][c][1], aq[t][c][2], aq[t][c][3],
                             kb[c][0], kb[c][1], s0, s1, s2, s3);
                }
                s[st][t][0] = s0; s[st][t][1] = s1; s[st][t][2] = s2; s[st][t][3] = s3;
            }
        };

        // ---- helper to do exp + PV for chunk kc from stage st ----
        auto pv_stage = [&](int st, int kc) {
            const float* vr0 = sV[cur] + (kc * 8 + 2 * i) * VSTRIDE;
            const float* vr1 = vr0 + VSTRIDE;
            u32 vb[4][2];
            #pragma unroll
            for (int nt = 0; nt < 4; nt++) {
                vb[nt][0] = __float_as_uint(vr0[nt * 8 + g]);
                vb[nt][1] = __float_as_uint(vr1[nt * 8 + g]);
            }
            #pragma unroll
            for (int t = 0; t < 2; t++) {
                float e0 = ex2f(s[st][t][0]);
                float e1 = ex2f(s[st][t][1]);
                float e2 = ex2f(s[st][t][2]);
                float e3 = ex2f(s[st][t][3]);
                lac[t][0] += e0 + e1;
                lac[t][1] += e2 + e3;
                // P frag: raw fp32 bits as tf32 (HW truncates mantissa)
                u32 p0 = __float_as_uint(e0);
                u32 p1 = __float_as_uint(e2);
                u32 p2 = __float_as_uint(e1);
                u32 p3 = __float_as_uint(e3);
                #pragma unroll
                for (int nt = 0; nt < 4; nt++) {
                    mma_tf32(o[t][nt][0], o[t][nt][1], o[t][nt][2], o[t][nt][3],
                             p0, p1, p2, p3, vb[nt][0], vb[nt][1],
                             o[t][nt][0], o[t][nt][1], o[t][nt][2], o[t][nt][3]);
                }
            }
        };

        // ---- 2-stage pipelined chunk loop ----
        qk_stage(0, 0);
        #pragma unroll
        for (int kc = 0; kc < NC; kc++) {
            int stc = kc & 1;
            if (kc + 1 < NC) qk_stage(stc ^ 1, kc + 1);   // QK of next chunk FIRST
            pv_stage(stc, kc);                            // exp+PV of current chunk
        }
    }

    // ---- epilogue: reduce l, normalize, residual, LayerNorm, store ----
    #pragma unroll
    for (int t = 0; t < 2; t++) {
        float l0 = lac[t][0], l1 = lac[t][1];
        l0 += __shfl_xor_sync(0xFFFFFFFFu, l0, 1);
        l0 += __shfl_xor_sync(0xFFFFFFFFu, l0, 2);
        l1 += __shfl_xor_sync(0xFFFFFFFFu, l1, 1);
        l1 += __shfl_xor_sync(0xFFFFFFFFu, l1, 2);
        float inv0 = 1.f / l0;
        float inv1 = 1.f / l1;

        #pragma unroll
        for (int half = 0; half < 2; half++) {
            int   row  = qbase + t * 16 + g + half * 8;
            float invl = half == 0 ? inv0 : inv1;
            int   r0   = half == 0 ? 0 : 2;

            const float2* qr = (const float2*)(ques + ((size_t)b * LQ + row) * DIN);
            float x[4][2];
            float ssum = 0.f;
            #pragma unroll
            for (int nt = 0; nt < 4; nt++) {
                float2 qv = qr[nt * 4 + i];
                x[nt][0] = o[t][nt][r0]     * invl + qv.x;
                x[nt][1] = o[t][nt][r0 + 1] * invl + qv.y;
                ssum += x[nt][0] + x[nt][1];
            }
            ssum += __shfl_xor_sync(0xFFFFFFFFu, ssum, 1);
            ssum += __shfl_xor_sync(0xFFFFFFFFu, ssum, 2);
            float m = ssum * (1.f / DIN);
            float v = 0.f;
            #pragma unroll
            for (int nt = 0; nt < 4; nt++) {
                float d0 = x[nt][0] - m, d1 = x[nt][1] - m;
                v += d0 * d0 + d1 * d1;
            }
            v += __shfl_xor_sync(0xFFFFFFFFu, v, 1);
            v += __shfl_xor_sync(0xFFFFFFFFu, v, 2);
            float rs = rsqrtf(v * (1.f / DIN) + EPS);

            float2* po = (float2*)(out + ((size_t)b * LQ + row) * DIN);
            #pragma unroll
            for (int nt = 0; nt < 4; nt++) {
                int col = nt * 8 + 2 * i;
                float2 tt;
                tt.x = (x[nt][0] - m) * rs * __ldg(go + col)     + __ldg(bo + col);
                tt.y = (x[nt][1] - m) * rs * __ldg(go + col + 1) + __ldg(bo + col + 1);
                po[nt * 4 + i] = tt;
            }
        }
    }
}

// ---------------------------------------------------------------------------
extern "C" void kernel_launch(void* const* d_in, const int* in_sizes, int n_in,
                              void* d_out, int out_size)
{
    const float* vals = (const float*)d_in[0];
    const float* keys = (const float*)d_in[1];
    const float* ques = (const float*)d_in[2];
    const void*  mask = d_in[3];
    const float* Wv   = (const float*)d_in[4];
    const float* Wk   = (const float*)d_in[5];
    const float* Wq   = (const float*)d_in[6];
    const float* gk   = (const float*)d_in[7];
    const float* bk   = (const float*)d_in[8];
    const float* gq   = (const float*)d_in[9];
    const float* bq   = (const float*)d_in[10];
    const float* go   = (const float*)d_in[11];
    const float* bo   = (const float*)d_in[12];
    float* out = (float*)d_out;

    dim3 pgrid((NB * LK) / 256, 3);
    proj_kernel<<<pgrid, 256>>>(vals, keys, ques, Wv, Wk, Wq, gk, bk, gq, bq);

    dim3 grid(LQ / 128, NB);
    attn_kernel<<<grid, 128>>>(mask, ques, go, bo, out);
}

// round 9
// speedup vs baseline: 1.3662x; 1.3662x over previous
#include <cuda_runtime.h>
#include <cstdint>

// Problem constants
#define NB   32
#define LQ   2048
#define LK   2048
#define DIN  32
#define DKQ  20
#define EPS  1e-5f
// fold 1/sqrt(20) * log2(e) into q so scores are in log2 domain
#define QSCALE 0.32258572299984063f   // log2(e)/sqrt(20)
#define BIAS_MASKED (-1e30f)

// bf16 storage strides (in u32 words = bf16 pairs)
#define KW 20   // K row: 16 real words (32 bf16: 20 feats + bias pair @10 + pad) + 4 pad -> 80B
#define VW 20   // V row: 16 real words (32 bf16 dims) + 4 pad -> 80B
#define QW 16   // Q row: 16 words (32 bf16) = 64B

typedef unsigned int u32;

// Scratch (allocation-free rule: __device__ globals), bf16 pairs as u32
__device__ u32 d_kb[(size_t)NB * LK * KW];
__device__ u32 d_vb[(size_t)NB * LK * VW];
__device__ u32 d_qb[(size_t)NB * LQ * QW];

__device__ __forceinline__ float ex2f(float x) {
    float r; asm("ex2.approx.f32 %0, %1;" : "=f"(r) : "f"(x));
    return r;
}
// pack two f32 -> bf16x2 (lo = first arg)
__device__ __forceinline__ u32 pack_bf(float lo, float hi) {
    u32 d; asm("cvt.rn.bf16x2.f32 %0, %1, %2;" : "=r"(d) : "f"(hi), "f"(lo));
    return d;
}
// m16n8k16 bf16 mma: D = A*B + C (fp32 accum)
__device__ __forceinline__ void mma_bf16(
    float& d0, float& d1, float& d2, float& d3,
    u32 a0, u32 a1, u32 a2, u32 a3, u32 b0, u32 b1,
    float c0, float c1, float c2, float c3)
{
    asm("mma.sync.aligned.m16n8k16.row.col.f32.bf16.bf16.f32 "
        "{%0,%1,%2,%3},{%4,%5,%6,%7},{%8,%9},{%10,%11,%12,%13};"
        : "=f"(d0), "=f"(d1), "=f"(d2), "=f"(d3)
        : "r"(a0), "r"(a1), "r"(a2), "r"(a3), "r"(b0), "r"(b1),
          "f"(c0), "f"(c1), "f"(c2), "f"(c3));
}
__device__ __forceinline__ void cp16(u32 dst, const void* src) {
    asm volatile("cp.async.cg.shared.global [%0], [%1], 16;" :: "r"(dst), "l"(src));
}
#define CP_COMMIT() asm volatile("cp.async.commit_group;")
#define CP_WAIT0()  asm volatile("cp.async.wait_group 0;")

// ---------------------------------------------------------------------------
// Kernel 1: projections -> bf16, split 3 ways by blockIdx.y (0=V, 1=K, 2=Q).
// K rows carry the mask bias at feature 20 (Q has 1.0 there).
// ---------------------------------------------------------------------------
__global__ __launch_bounds__(256) void proj_kernel(
    const float* __restrict__ vals, const float* __restrict__ keys,
    const float* __restrict__ ques, const void* __restrict__ mask_raw,
    const float* __restrict__ Wv, const float* __restrict__ Wk, const float* __restrict__ Wq,
    const float* __restrict__ gk, const float* __restrict__ bk,
    const float* __restrict__ gq, const float* __restrict__ bq)
{
    __shared__ float sW[DIN * DIN];
    __shared__ float sg[DKQ], sb[DKQ];
    __shared__ int s_is_byte;

    int tid  = threadIdx.x;
    int task = blockIdx.y;
    size_t r = (size_t)blockIdx.x * 256 + tid;

    if (task == 0) {
        for (int i = tid; i < DIN * DIN; i += 256) sW[i] = Wv[i];
        __syncthreads();

        float x[DIN];
        const float4* p4 = (const float4*)(vals + r * DIN);
        #pragma unroll
        for (int i = 0; i < 8; i++) {
            float4 t = p4[i];
            x[4*i] = t.x; x[4*i+1] = t.y; x[4*i+2] = t.z; x[4*i+3] = t.w;
        }
        float outr[DIN];
        #pragma unroll
        for (int o = 0; o < DIN; o++) {
            float acc = 0.f;
            #pragma unroll
            for (int d = 0; d < DIN; d++) acc += x[d] * sW[o * DIN + d];
            outr[o] = acc;
        }
        u32 wv[KW];
        #pragma unroll
        for (int p = 0; p < 16; p++) wv[p] = pack_bf(outr[2*p], outr[2*p+1]);
        #pragma unroll
        for (int p = 16; p < VW; p++) wv[p] = 0u;
        uint4* o4 = (uint4*)(d_vb + r * VW);
        #pragma unroll
        for (int i = 0; i < 5; i++)
            o4[i] = make_uint4(wv[4*i], wv[4*i+1], wv[4*i+2], wv[4*i+3]);
    } else {
        const float* W  = (task == 1) ? Wk : Wq;
        const float* gg = (task == 1) ? gk : gq;
        const float* bb = (task == 1) ? bk : bq;
        const float* in = (task == 1) ? keys : ques;
        for (int i = tid; i < DKQ * DIN; i += 256) sW[i] = W[i];
        if (tid < DKQ) { sg[tid] = gg[tid]; sb[tid] = bb[tid]; }
        if (task == 1 && tid == 0) {
            // Detect mask storage: numpy bool (1 byte) vs int32 coercion.
            const unsigned int* wd = (const unsigned int*)mask_raw;
            unsigned int acc = 0;
            for (int k = 0; k < 64; k++) acc |= wd[k] & 0xFFFFFF00u;
            s_is_byte = (acc != 0u);
        }
        __syncthreads();

        float x[DIN];
        const float4* p4 = (const float4*)(in + r * DIN);
        #pragma unroll
        for (int i = 0; i < 8; i++) {
            float4 t = p4[i];
            x[4*i] = t.x; x[4*i+1] = t.y; x[4*i+2] = t.z; x[4*i+3] = t.w;
        }
        float y[DKQ];
        #pragma unroll
        for (int o = 0; o < DKQ; o++) {
            float acc = 0.f;
            #pragma unroll
            for (int d = 0; d < DIN; d++) acc += x[d] * sW[o * DIN + d];
            y[o] = acc;
        }
        float m = 0.f;
        #pragma unroll
        for (int c = 0; c < DKQ; c++) m += y[c];
        m *= (1.f / DKQ);
        float v = 0.f;
        #pragma unroll
        for (int c = 0; c < DKQ; c++) { float d = y[c] - m; v += d * d; }
        v *= (1.f / DKQ);
        float rs = rsqrtf(v + EPS);

        if (task == 1) {
            #pragma unroll
            for (int c = 0; c < DKQ; c++) y[c] = (y[c] - m) * rs * sg[c] + sb[c];
            int mv = s_is_byte ? (int)((const unsigned char*)mask_raw)[r]
                               : ((const int*)mask_raw)[r];
            float bias = mv ? BIAS_MASKED : 0.f;   // True masks OUT
            u32 wv[KW];
            #pragma unroll
            for (int p = 0; p < 10; p++) wv[p] = pack_bf(y[2*p], y[2*p+1]);
            wv[10] = pack_bf(bias, 0.f);
            #pragma unroll
            for (int p = 11; p < KW; p++) wv[p] = 0u;
            uint4* o4 = (uint4*)(d_kb + r * KW);
            #pragma unroll
            for (int i = 0; i < 5; i++)
                o4[i] = make_uint4(wv[4*i], wv[4*i+1], wv[4*i+2], wv[4*i+3]);
        } else {
            #pragma unroll
            for (int c = 0; c < DKQ; c++)
                y[c] = ((y[c] - m) * rs * sg[c] + sb[c]) * QSCALE;
            u32 wv[QW];
            #pragma unroll
            for (int p = 0; p < 10; p++) wv[p] = pack_bf(y[2*p], y[2*p+1]);
            wv[10] = pack_bf(1.0f, 0.f);
            #pragma unroll
            for (int p = 11; p < QW; p++) wv[p] = 0u;
            uint4* o4 = (uint4*)(d_qb + r * QW);
            #pragma unroll
            for (int i = 0; i < 4; i++)
                o4[i] = make_uint4(wv[4*i], wv[4*i+1], wv[4*i+2], wv[4*i+3]);
        }
    }
}

// ---------------------------------------------------------------------------
// Kernel 2: flash attention, bf16 m16n8k16 mma + ldmatrix, cp.async
// double-buffered TS=64 tiles. CTA = 128 thr = 4 warps; warp: 32 queries
// (2 m16 tiles); CTA: 128 queries. grid=(16,32). Mask bias lives in K[20].
// ---------------------------------------------------------------------------
#define TS 64
#define NT (LK / TS)
#define T16 (TS * KW / 4)   // 320 uint4 per tile (K and V identical)

__global__ __launch_bounds__(128) void attn_kernel(
    const float* __restrict__ ques,
    const float* __restrict__ go, const float* __restrict__ bo,
    float* __restrict__ out)
{
    __shared__ u32 sK[2][TS * KW];   // 2 x 5120 B
    __shared__ u32 sV[2][TS * VW];   // 2 x 5120 B

    int tid  = threadIdx.x;
    int w    = tid >> 5;
    int lane = tid & 31;
    int g    = lane >> 2;   // group id (0..7)
    int i    = lane & 3;    // thread in group (0..3)
    int b    = blockIdx.y;
    int qbase = blockIdx.x * 128 + w * 32;

    // ---- Q fragments: two m16 tiles x two k16 chunks, in registers ----
    u32 aq[2][2][4];
    #pragma unroll
    for (int t = 0; t < 2; t++) {
        const u32* q0p = d_qb + ((size_t)b * LQ + qbase + t * 16 + g) * QW;
        const u32* q1p = q0p + 8 * QW;
        #pragma unroll
        for (int c = 0; c < 2; c++) {
            aq[t][c][0] = q0p[8 * c + i];
            aq[t][c][1] = q1p[8 * c + i];
            aq[t][c][2] = q0p[8 * c + i + 4];
            aq[t][c][3] = q1p[8 * c + i + 4];
        }
    }

    float o[2][4][4];
    #pragma unroll
    for (int t = 0; t < 2; t++)
        #pragma unroll
        for (int nt = 0; nt < 4; nt++)
            #pragma unroll
            for (int r = 0; r < 4; r++) o[t][nt][r] = 0.f;
    float lac[2][2];
    lac[0][0] = lac[0][1] = lac[1][0] = lac[1][1] = 0.f;

    const u32* kgl = d_kb + (size_t)b * LK * KW;
    const u32* vgl = d_vb + (size_t)b * LK * VW;

    u32 sK_u[2], sV_u[2];
    sK_u[0] = (u32)__cvta_generic_to_shared(&sK[0][0]);
    sK_u[1] = (u32)__cvta_generic_to_shared(&sK[1][0]);
    sV_u[0] = (u32)__cvta_generic_to_shared(&sV[0][0]);
    sV_u[1] = (u32)__cvta_generic_to_shared(&sV[1][0]);

    // ---- preamble: async load tile 0 ----
    {
        #pragma unroll
        for (int rr = 0; rr < 3; rr++) {
            int idx = tid + rr * 128;
            if (idx < T16) {
                cp16(sK_u[0] + idx * 16, kgl + idx * 4);
                cp16(sV_u[0] + idx * 16, vgl + idx * 4);
            }
        }
        CP_COMMIT();
    }

    for (int t0 = 0; t0 < NT; t0++) {
        int cur = t0 & 1;
        CP_WAIT0();
        __syncthreads();   // tile t0 ready; all warps done with buffer we refill

        // prefetch tile t0+1 (overlaps with compute below)
        if (t0 + 1 < NT) {
            int nxt = cur ^ 1;
            const u32* kg2 = kgl + (size_t)(t0 + 1) * TS * KW;
            const u32* vg2 = vgl + (size_t)(t0 + 1) * TS * VW;
            #pragma unroll
            for (int rr = 0; rr < 3; rr++) {
                int idx = tid + rr * 128;
                if (idx < T16) {
                    cp16(sK_u[nxt] + idx * 16, kg2 + idx * 4);
                    cp16(sV_u[nxt] + idx * 16, vg2 + idx * 4);
                }
            }
            CP_COMMIT();
        }

        #pragma unroll
        for (int kg = 0; kg < TS / 16; kg++) {
            // ---- K fragments: 8-key groups A (keys kg*16+0..7) and B (+8..15)
            const u32* kA = &sK[cur][(kg * 16 + g) * KW];
            const u32* kB = kA + 8 * KW;
            u32 kbA[4], kbB[4];
            kbA[0] = kA[i];     kbA[1] = kA[i + 4];
            kbA[2] = kA[8 + i]; kbA[3] = kA[12 + i];
            kbB[0] = kB[i];     kbB[1] = kB[i + 4];
            kbB[2] = kB[8 + i]; kbB[3] = kB[12 + i];

            // ---- V fragments via ldmatrix.x4.trans (16 keys x 32 cols) ----
            u32 vb0[4], vb1[4];
            {
                int rrow = lane & 7, mm = lane >> 3;
                u32 a1 = sV_u[cur] + ((kg * 16 + rrow) * VW + mm * 4) * 4;
                u32 a2 = a1 + 8 * VW * 4;
                asm volatile("ldmatrix.sync.aligned.m8n8.x4.trans.shared.b16 "
                             "{%0,%1,%2,%3}, [%4];"
                    : "=r"(vb0[0]), "=r"(vb0[1]), "=r"(vb0[2]), "=r"(vb0[3]) : "r"(a1));
                asm volatile("ldmatrix.sync.aligned.m8n8.x4.trans.shared.b16 "
                             "{%0,%1,%2,%3}, [%4];"
                    : "=r"(vb1[0]), "=r"(vb1[1]), "=r"(vb1[2]), "=r"(vb1[3]) : "r"(a2));
            }

            #pragma unroll
            for (int t = 0; t < 2; t++) {
                // QK^T for both 8-key groups (bias included via K[20])
                float sA0 = 0.f, sA1 = 0.f, sA2 = 0.f, sA3 = 0.f;
                float sB0 = 0.f, sB1 = 0.f, sB2 = 0.f, sB3 = 0.f;
                mma_bf16(sA0, sA1, sA2, sA3,
                         aq[t][0][0], aq[t][0][1], aq[t][0][2], aq[t][0][3],
                         kbA[0], kbA[1], sA0, sA1, sA2, sA3);
                mma_bf16(sA0, sA1, sA2, sA3,
                         aq[t][1][0], aq[t][1][1], aq[t][1][2], aq[t][1][3],
                         kbA[2], kbA[3], sA0, sA1, sA2, sA3);
                mma_bf16(sB0, sB1, sB2, sB3,
                         aq[t][0][0], aq[t][0][1], aq[t][0][2], aq[t][0][3],
                         kbB[0], kbB[1], sB0, sB1, sB2, sB3);
                mma_bf16(sB0, sB1, sB2, sB3,
                         aq[t][1][0], aq[t][1][1], aq[t][1][2], aq[t][1][3],
                         kbB[2], kbB[3], sB0, sB1, sB2, sB3);

                float eA0 = ex2f(sA0), eA1 = ex2f(sA1);
                float eA2 = ex2f(sA2), eA3 = ex2f(sA3);
                float eB0 = ex2f(sB0), eB1 = ex2f(sB1);
                float eB2 = ex2f(sB2), eB3 = ex2f(sB3);
                lac[t][0] += (eA0 + eA1) + (eB0 + eB1);   // row g
                lac[t][1] += (eA2 + eA3) + (eB2 + eB3);   // row g+8

                // P A-frag (16 queries x 16 keys), packed bf16x2
                u32 pa0 = pack_bf(eA0, eA1);   // row g,   keys 2i,2i+1
                u32 pa1 = pack_bf(eA2, eA3);   // row g+8
                u32 pa2 = pack_bf(eB0, eB1);   // row g,   keys 8+2i,8+2i+1
                u32 pa3 = pack_bf(eB2, eB3);   // row g+8

                #pragma unroll
                for (int nt = 0; nt < 4; nt++) {
                    mma_bf16(o[t][nt][0], o[t][nt][1], o[t][nt][2], o[t][nt][3],
                             pa0, pa1, pa2, pa3, vb0[nt], vb1[nt],
                             o[t][nt][0], o[t][nt][1], o[t][nt][2], o[t][nt][3]);
                }
            }
        }
    }

    // ---- epilogue: reduce l, normalize, residual, LayerNorm, store ----
    #pragma unroll
    for (int t = 0; t < 2; t++) {
        float l0 = lac[t][0], l1 = lac[t][1];
        l0 += __shfl_xor_sync(0xFFFFFFFFu, l0, 1);
        l0 += __shfl_xor_sync(0xFFFFFFFFu, l0, 2);
        l1 += __shfl_xor_sync(0xFFFFFFFFu, l1, 1);
        l1 += __shfl_xor_sync(0xFFFFFFFFu, l1, 2);
        float inv0 = 1.f / l0;
        float inv1 = 1.f / l1;

        #pragma unroll
        for (int half = 0; half < 2; half++) {
            int   row  = qbase + t * 16 + g + half * 8;
            float invl = half == 0 ? inv0 : inv1;
            int   r0   = half == 0 ? 0 : 2;

            const float2* qr = (const float2*)(ques + ((size_t)b * LQ + row) * DIN);
            float x[4][2];
            float ssum = 0.f;
            #pragma unroll
            for (int nt = 0; nt < 4; nt++) {
                float2 qv = qr[nt * 4 + i];
                x[nt][0] = o[t][nt][r0]     * invl + qv.x;
                x[nt][1] = o[t][nt][r0 + 1] * invl + qv.y;
                ssum += x[nt][0] + x[nt][1];
            }
            ssum += __shfl_xor_sync(0xFFFFFFFFu, ssum, 1);
            ssum += __shfl_xor_sync(0xFFFFFFFFu, ssum, 2);
            float m = ssum * (1.f / DIN);
            float v = 0.f;
            #pragma unroll
            for (int nt = 0; nt < 4; nt++) {
                float d0 = x[nt][0] - m, d1 = x[nt][1] - m;
                v += d0 * d0 + d1 * d1;
            }
            v += __shfl_xor_sync(0xFFFFFFFFu, v, 1);
            v += __shfl_xor_sync(0xFFFFFFFFu, v, 2);
            float rs = rsqrtf(v * (1.f / DIN) + EPS);

            float2* po = (float2*)(out + ((size_t)b * LQ + row) * DIN);
            #pragma unroll
            for (int nt = 0; nt < 4; nt++) {
                int col = nt * 8 + 2 * i;
                float2 tt;
                tt.x = (x[nt][0] - m) * rs * __ldg(go + col)     + __ldg(bo + col);
                tt.y = (x[nt][1] - m) * rs * __ldg(go + col + 1) + __ldg(bo + col + 1);
                po[nt * 4 + i] = tt;
            }
        }
    }
}

// ---------------------------------------------------------------------------
extern "C" void kernel_launch(void* const* d_in, const int* in_sizes, int n_in,
                              void* d_out, int out_size)
{
    const float* vals = (const float*)d_in[0];
    const float* keys = (const float*)d_in[1];
    const float* ques = (const float*)d_in[2];
    const void*  mask = d_in[3];
    const float* Wv   = (const float*)d_in[4];
    const float* Wk   = (const float*)d_in[5];
    const float* Wq   = (const float*)d_in[6];
    const float* gk   = (const float*)d_in[7];
    const float* bk   = (const float*)d_in[8];
    const float* gq   = (const float*)d_in[9];
    const float* bq   = (const float*)d_in[10];
    const float* go   = (const float*)d_in[11];
    const float* bo   = (const float*)d_in[12];
    float* out = (float*)d_out;

    dim3 pgrid((NB * LK) / 256, 3);
    proj_kernel<<<pgrid, 256>>>(vals, keys, ques, mask, Wv, Wk, Wq, gk, bk, gq, bq);

    dim3 grid(LQ / 128, NB);
    attn_kernel<<<grid, 128>>>(ques, go, bo, out);
}

// round 10
// speedup vs baseline: 1.5714x; 1.1502x over previous
#include <cuda_runtime.h>
#include <cstdint>

// Problem constants
#define NB   32
#define LQ   2048
#define LK   2048
#define DIN  32
#define DKQ  20
#define EPS  1e-5f
// fold 1/sqrt(20) * log2(e) into q so scores are in log2 domain
#define QSCALE 0.32258572299984063f   // log2(e)/sqrt(20)
#define BIAS_MASKED (-60000.0f)       // f16-finite; ex2 -> exactly 0

// f16 storage strides (in u32 words = f16 pairs)
#define KW 20   // K row: feats 0..19, bias@20, zero-pad to 40 f16 -> 80B
#define VW 20   // V row: dims 0..31, ones-col@32, zero-pad to 40 f16 -> 80B
#define QW 16   // Q row: feats 0..19, 1.0@20, zero-pad to 32 f16 -> 64B

typedef unsigned int u32;

// Scratch (allocation-free rule: __device__ globals), f16 pairs as u32
__device__ u32 d_kb[(size_t)NB * LK * KW];
__device__ u32 d_vb[(size_t)NB * LK * VW];
__device__ u32 d_qb[(size_t)NB * LQ * QW];

// pack two f32 -> f16x2 (lo = first arg)
__device__ __forceinline__ u32 pack_f16(float lo, float hi) {
    u32 d; asm("cvt.rn.f16x2.f32 %0, %1, %2;" : "=r"(d) : "f"(hi), "f"(lo));
    return d;
}
// dual exp2 on packed f16x2
__device__ __forceinline__ u32 ex2h2(u32 a) {
    u32 d; asm("ex2.approx.f16x2 %0, %1;" : "=r"(d) : "r"(a));
    return d;
}
// m16n8k16 f16 mma: D = A*B + C (fp32 accum)
__device__ __forceinline__ void mma_f16(
    float& d0, float& d1, float& d2, float& d3,
    u32 a0, u32 a1, u32 a2, u32 a3, u32 b0, u32 b1,
    float c0, float c1, float c2, float c3)
{
    asm("mma.sync.aligned.m16n8k16.row.col.f32.f16.f16.f32 "
        "{%0,%1,%2,%3},{%4,%5,%6,%7},{%8,%9},{%10,%11,%12,%13};"
        : "=f"(d0), "=f"(d1), "=f"(d2), "=f"(d3)
        : "r"(a0), "r"(a1), "r"(a2), "r"(a3), "r"(b0), "r"(b1),
          "f"(c0), "f"(c1), "f"(c2), "f"(c3));
}
__device__ __forceinline__ void cp16(u32 dst, const void* src) {
    asm volatile("cp.async.cg.shared.global [%0], [%1], 16;" :: "r"(dst), "l"(src));
}
#define CP_COMMIT() asm volatile("cp.async.commit_group;")
#define CP_WAIT0()  asm volatile("cp.async.wait_group 0;")

// ---------------------------------------------------------------------------
// Kernel 1: projections -> f16, split 3 ways by blockIdx.y (0=V, 1=K, 2=Q).
// K rows carry the mask bias at feature 20 (Q has 1.0 there).
// V rows carry a ones-column at dim 32 (softmax denominator via tensor pipe).
// ---------------------------------------------------------------------------
__global__ __launch_bounds__(256) void proj_kernel(
    const float* __restrict__ vals, const float* __restrict__ keys,
    const float* __restrict__ ques, const void* __restrict__ mask_raw,
    const float* __restrict__ Wv, const float* __restrict__ Wk, const float* __restrict__ Wq,
    const float* __restrict__ gk, const float* __restrict__ bk,
    const float* __restrict__ gq, const float* __restrict__ bq)
{
    __shared__ float sW[DIN * DIN];
    __shared__ float sg[DKQ], sb[DKQ];
    __shared__ int s_is_byte;

    int tid  = threadIdx.x;
    int task = blockIdx.y;
    size_t r = (size_t)blockIdx.x * 256 + tid;

    if (task == 0) {
        for (int i = tid; i < DIN * DIN; i += 256) sW[i] = Wv[i];
        __syncthreads();

        float x[DIN];
        const float4* p4 = (const float4*)(vals + r * DIN);
        #pragma unroll
        for (int i = 0; i < 8; i++) {
            float4 t = p4[i];
            x[4*i] = t.x; x[4*i+1] = t.y; x[4*i+2] = t.z; x[4*i+3] = t.w;
        }
        float outr[DIN];
        #pragma unroll
        for (int o = 0; o < DIN; o++) {
            float acc = 0.f;
            #pragma unroll
            for (int d = 0; d < DIN; d++) acc += x[d] * sW[o * DIN + d];
            outr[o] = acc;
        }
        u32 wv[VW];
        #pragma unroll
        for (int p = 0; p < 16; p++) wv[p] = pack_f16(outr[2*p], outr[2*p+1]);
        wv[16] = pack_f16(1.0f, 0.f);      // ones-column @ dim 32
        #pragma unroll
        for (int p = 17; p < VW; p++) wv[p] = 0u;
        uint4* o4 = (uint4*)(d_vb + r * VW);
        #pragma unroll
        for (int i = 0; i < 5; i++)
            o4[i] = make_uint4(wv[4*i], wv[4*i+1], wv[4*i+2], wv[4*i+3]);
    } else {
        const float* W  = (task == 1) ? Wk : Wq;
        const float* gg = (task == 1) ? gk : gq;
        const float* bb = (task == 1) ? bk : bq;
        const float* in = (task == 1) ? keys : ques;
        for (int i = tid; i < DKQ * DIN; i += 256) sW[i] = W[i];
        if (tid < DKQ) { sg[tid] = gg[tid]; sb[tid] = bb[tid]; }
        if (task == 1 && tid == 0) {
            // Detect mask storage: numpy bool (1 byte) vs int32 coercion.
            const unsigned int* wd = (const unsigned int*)mask_raw;
            unsigned int acc = 0;
            for (int k = 0; k < 64; k++) acc |= wd[k] & 0xFFFFFF00u;
            s_is_byte = (acc != 0u);
        }
        __syncthreads();

        float x[DIN];
        const float4* p4 = (const float4*)(in + r * DIN);
        #pragma unroll
        for (int i = 0; i < 8; i++) {
            float4 t = p4[i];
            x[4*i] = t.x; x[4*i+1] = t.y; x[4*i+2] = t.z; x[4*i+3] = t.w;
        }
        float y[DKQ];
        #pragma unroll
        for (int o = 0; o < DKQ; o++) {
            float acc = 0.f;
            #pragma unroll
            for (int d = 0; d < DIN; d++) acc += x[d] * sW[o * DIN + d];
            y[o] = acc;
        }
        float m = 0.f;
        #pragma unroll
        for (int c = 0; c < DKQ; c++) m += y[c];
        m *= (1.f / DKQ);
        float v = 0.f;
        #pragma unroll
        for (int c = 0; c < DKQ; c++) { float d = y[c] - m; v += d * d; }
        v *= (1.f / DKQ);
        float rs = rsqrtf(v + EPS);

        if (task == 1) {
            #pragma unroll
            for (int c = 0; c < DKQ; c++) y[c] = (y[c] - m) * rs * sg[c] + sb[c];
            int mv = s_is_byte ? (int)((const unsigned char*)mask_raw)[r]
                               : ((const int*)mask_raw)[r];
            float bias = mv ? BIAS_MASKED : 0.f;   // True masks OUT
            u32 wv[KW];
            #pragma unroll
            for (int p = 0; p < 10; p++) wv[p] = pack_f16(y[2*p], y[2*p+1]);
            wv[10] = pack_f16(bias, 0.f);
            #pragma unroll
            for (int p = 11; p < KW; p++) wv[p] = 0u;
            uint4* o4 = (uint4*)(d_kb + r * KW);
            #pragma unroll
            for (int i = 0; i < 5; i++)
                o4[i] = make_uint4(wv[4*i], wv[4*i+1], wv[4*i+2], wv[4*i+3]);
        } else {
            #pragma unroll
            for (int c = 0; c < DKQ; c++)
                y[c] = ((y[c] - m) * rs * sg[c] + sb[c]) * QSCALE;
            u32 wv[QW];
            #pragma unroll
            for (int p = 0; p < 10; p++) wv[p] = pack_f16(y[2*p], y[2*p+1]);
            wv[10] = pack_f16(1.0f, 0.f);
            #pragma unroll
            for (int p = 11; p < QW; p++) wv[p] = 0u;
            uint4* o4 = (uint4*)(d_qb + r * QW);
            #pragma unroll
            for (int i = 0; i < 4; i++)
                o4[i] = make_uint4(wv[4*i], wv[4*i+1], wv[4*i+2], wv[4*i+3]);
        }
    }
}

// ---------------------------------------------------------------------------
// Kernel 2: flash attention, f16 m16n8k16 mma + ldmatrix, cp.async
// double-buffered TS=64 tiles. exp via ex2.approx.f16x2 (2 scores/MUFU op),
// softmax denominator via V ones-column (no scalar adds).
// CTA = 128 thr = 4 warps; warp: 32 queries; CTA: 128 queries. grid=(16,32).
// ---------------------------------------------------------------------------
#define TS 64
#define NT (LK / TS)
#define T16 (TS * KW / 4)   // 320 uint4 per tile (K and V identical)

__global__ __launch_bounds__(128) void attn_kernel(
    const float* __restrict__ ques,
    const float* __restrict__ go, const float* __restrict__ bo,
    float* __restrict__ out)
{
    __shared__ u32 sK[2][TS * KW];   // 2 x 5120 B
    __shared__ u32 sV[2][TS * VW];   // 2 x 5120 B

    int tid  = threadIdx.x;
    int w    = tid >> 5;
    int lane = tid & 31;
    int g    = lane >> 2;   // group id (0..7)
    int i    = lane & 3;    // thread in group (0..3)
    int b    = blockIdx.y;
    int qbase = blockIdx.x * 128 + w * 32;

    // ---- Q fragments: two m16 tiles x two k16 chunks, in registers ----
    u32 aq[2][2][4];
    #pragma unroll
    for (int t = 0; t < 2; t++) {
        const u32* q0p = d_qb + ((size_t)b * LQ + qbase + t * 16 + g) * QW;
        const u32* q1p = q0p + 8 * QW;
        #pragma unroll
        for (int c = 0; c < 2; c++) {
            aq[t][c][0] = q0p[8 * c + i];
            aq[t][c][1] = q1p[8 * c + i];
            aq[t][c][2] = q0p[8 * c + i + 4];
            aq[t][c][3] = q1p[8 * c + i + 4];
        }
    }

    // o[t][nt] nt=0..3: output dims; nt=4: ones-column (denominator)
    float o[2][5][4];
    #pragma unroll
    for (int t = 0; t < 2; t++)
        #pragma unroll
        for (int nt = 0; nt < 5; nt++)
            #pragma unroll
            for (int r = 0; r < 4; r++) o[t][nt][r] = 0.f;

    const u32* kgl = d_kb + (size_t)b * LK * KW;
    const u32* vgl = d_vb + (size_t)b * LK * VW;

    u32 sK_u[2], sV_u[2];
    sK_u[0] = (u32)__cvta_generic_to_shared(&sK[0][0]);
    sK_u[1] = (u32)__cvta_generic_to_shared(&sK[1][0]);
    sV_u[0] = (u32)__cvta_generic_to_shared(&sV[0][0]);
    sV_u[1] = (u32)__cvta_generic_to_shared(&sV[1][0]);

    // ---- preamble: async load tile 0 ----
    {
        #pragma unroll
        for (int rr = 0; rr < 3; rr++) {
            int idx = tid + rr * 128;
            if (idx < T16) {
                cp16(sK_u[0] + idx * 16, kgl + idx * 4);
                cp16(sV_u[0] + idx * 16, vgl + idx * 4);
            }
        }
        CP_COMMIT();
    }

    for (int t0 = 0; t0 < NT; t0++) {
        int cur = t0 & 1;
        CP_WAIT0();
        __syncthreads();   // tile t0 ready; all warps done with buffer we refill

        // prefetch tile t0+1 (overlaps with compute below)
        if (t0 + 1 < NT) {
            int nxt = cur ^ 1;
            const u32* kg2 = kgl + (size_t)(t0 + 1) * TS * KW;
            const u32* vg2 = vgl + (size_t)(t0 + 1) * TS * VW;
            #pragma unroll
            for (int rr = 0; rr < 3; rr++) {
                int idx = tid + rr * 128;
                if (idx < T16) {
                    cp16(sK_u[nxt] + idx * 16, kg2 + idx * 4);
                    cp16(sV_u[nxt] + idx * 16, vg2 + idx * 4);
                }
            }
            CP_COMMIT();
        }

        #pragma unroll
        for (int kg = 0; kg < TS / 16; kg++) {
            // ---- K fragments: 8-key groups A (keys kg*16+0..7) and B (+8..15)
            const u32* kA = &sK[cur][(kg * 16 + g) * KW];
            const u32* kB = kA + 8 * KW;
            u32 kbA[4], kbB[4];
            kbA[0] = kA[i];     kbA[1] = kA[i + 4];
            kbA[2] = kA[8 + i]; kbA[3] = kA[12 + i];
            kbB[0] = kB[i];     kbB[1] = kB[i + 4];
            kbB[2] = kB[8 + i]; kbB[3] = kB[12 + i];

            // ---- V fragments: ldmatrix x4 (dims 0..31) + x2 (ones col 32..39)
            u32 vb0[4], vb1[4], vb40, vb41;
            {
                int rrow = lane & 7, mm = lane >> 3;
                u32 a1 = sV_u[cur] + ((kg * 16 + rrow) * VW + mm * 4) * 4;
                u32 a2 = a1 + 8 * VW * 4;
                asm volatile("ldmatrix.sync.aligned.m8n8.x4.trans.shared.b16 "
                             "{%0,%1,%2,%3}, [%4];"
                    : "=r"(vb0[0]), "=r"(vb0[1]), "=r"(vb0[2]), "=r"(vb0[3]) : "r"(a1));
                asm volatile("ldmatrix.sync.aligned.m8n8.x4.trans.shared.b16 "
                             "{%0,%1,%2,%3}, [%4];"
                    : "=r"(vb1[0]), "=r"(vb1[1]), "=r"(vb1[2]), "=r"(vb1[3]) : "r"(a2));
                u32 a3 = sV_u[cur] +
                    ((kg * 16 + (lane & 7) + ((lane >> 3) & 1) * 8) * VW + 16) * 4;
                asm volatile("ldmatrix.sync.aligned.m8n8.x2.trans.shared.b16 "
                             "{%0,%1}, [%2];"
                    : "=r"(vb40), "=r"(vb41) : "r"(a3));
            }

            #pragma unroll
            for (int t = 0; t < 2; t++) {
                // QK^T for both 8-key groups (bias included via K[20])
                float sA0 = 0.f, sA1 = 0.f, sA2 = 0.f, sA3 = 0.f;
                float sB0 = 0.f, sB1 = 0.f, sB2 = 0.f, sB3 = 0.f;
                mma_f16(sA0, sA1, sA2, sA3,
                        aq[t][0][0], aq[t][0][1], aq[t][0][2], aq[t][0][3],
                        kbA[0], kbA[1], sA0, sA1, sA2, sA3);
                mma_f16(sA0, sA1, sA2, sA3,
                        aq[t][1][0], aq[t][1][1], aq[t][1][2], aq[t][1][3],
                        kbA[2], kbA[3], sA0, sA1, sA2, sA3);
                mma_f16(sB0, sB1, sB2, sB3,
                        aq[t][0][0], aq[t][0][1], aq[t][0][2], aq[t][0][3],
                        kbB[0], kbB[1], sB0, sB1, sB2, sB3);
                mma_f16(sB0, sB1, sB2, sB3,
                        aq[t][1][0], aq[t][1][1], aq[t][1][2], aq[t][1][3],
                        kbB[2], kbB[3], sB0, sB1, sB2, sB3);

                // pack score pairs -> f16x2, dual-exp via one MUFU op each.
                // Resulting f16x2 IS the P A-fragment (no further packing).
                u32 pa0 = ex2h2(pack_f16(sA0, sA1));   // row g,   keys 2i,2i+1
                u32 pa1 = ex2h2(pack_f16(sA2, sA3));   // row g+8
                u32 pa2 = ex2h2(pack_f16(sB0, sB1));   // row g,   keys 8+2i..
                u32 pa3 = ex2h2(pack_f16(sB2, sB3));   // row g+8

                #pragma unroll
                for (int nt = 0; nt < 4; nt++) {
                    mma_f16(o[t][nt][0], o[t][nt][1], o[t][nt][2], o[t][nt][3],
                            pa0, pa1, pa2, pa3, vb0[nt], vb1[nt],
                            o[t][nt][0], o[t][nt][1], o[t][nt][2], o[t][nt][3]);
                }
                // ones-column: accumulates softmax denominator per row
                mma_f16(o[t][4][0], o[t][4][1], o[t][4][2], o[t][4][3],
                        pa0, pa1, pa2, pa3, vb40, vb41,
                        o[t][4][0], o[t][4][1], o[t][4][2], o[t][4][3]);
            }
        }
    }

    // ---- epilogue: broadcast l (ones-col, i==0 lanes), normalize, residual,
    //      LayerNorm, store ----
    #pragma unroll
    for (int t = 0; t < 2; t++) {
        // l lives at col 32 -> local col 0 -> lanes with i==0
        float l0 = __shfl_sync(0xFFFFFFFFu, o[t][4][0], lane & 28);  // row g
        float l1 = __shfl_sync(0xFFFFFFFFu, o[t][4][2], lane & 28);  // row g+8
        float inv0 = 1.f / l0;
        float inv1 = 1.f / l1;

        #pragma unroll
        for (int half = 0; half < 2; half++) {
            int   row  = qbase + t * 16 + g + half * 8;
            float invl = half == 0 ? inv0 : inv1;
            int   r0   = half == 0 ? 0 : 2;

            const float2* qr = (const float2*)(ques + ((size_t)b * LQ + row) * DIN);
            float x[4][2];
            float ssum = 0.f;
            #pragma unroll
            for (int nt = 0; nt < 4; nt++) {
                float2 qv = qr[nt * 4 + i];
                x[nt][0] = o[t][nt][r0]     * invl + qv.x;
                x[nt][1] = o[t][nt][r0 + 1] * invl + qv.y;
                ssum += x[nt][0] + x[nt][1];
            }
            ssum += __shfl_xor_sync(0xFFFFFFFFu, ssum, 1);
            ssum += __shfl_xor_sync(0xFFFFFFFFu, ssum, 2);
            float m = ssum * (1.f / DIN);
            float v = 0.f;
            #pragma unroll
            for (int nt = 0; nt < 4; nt++) {
                float d0 = x[nt][0] - m, d1 = x[nt][1] - m;
                v += d0 * d0 + d1 * d1;
            }
            v += __shfl_xor_sync(0xFFFFFFFFu, v, 1);
            v += __shfl_xor_sync(0xFFFFFFFFu, v, 2);
            float rs = rsqrtf(v * (1.f / DIN) + EPS);

            float2* po = (float2*)(out + ((size_t)b * LQ + row) * DIN);
            #pragma unroll
            for (int nt = 0; nt < 4; nt++) {
                int col = nt * 8 + 2 * i;
                float2 tt;
                tt.x = (x[nt][0] - m) * rs * __ldg(go + col)     + __ldg(bo + col);
                tt.y = (x[nt][1] - m) * rs * __ldg(go + col + 1) + __ldg(bo + col + 1);
                po[nt * 4 + i] = tt;
            }
        }
    }
}

// ---------------------------------------------------------------------------
extern "C" void kernel_launch(void* const* d_in, const int* in_sizes, int n_in,
                              void* d_out, int out_size)
{
    const float* vals = (const float*)d_in[0];
    const float* keys = (const float*)d_in[1];
    const float* ques = (const float*)d_in[2];
    const void*  mask = d_in[3];
    const float* Wv   = (const float*)d_in[4];
    const float* Wk   = (const float*)d_in[5];
    const float* Wq   = (const float*)d_in[6];
    const float* gk   = (const float*)d_in[7];
    const float* bk   = (const float*)d_in[8];
    const float* gq   = (const float*)d_in[9];
    const float* bq   = (const float*)d_in[10];
    const float* go   = (const float*)d_in[11];
    const float* bo   = (const float*)d_in[12];
    float* out = (float*)d_out;

    dim3 pgrid((NB * LK) / 256, 3);
    proj_kernel<<<pgrid, 256>>>(vals, keys, ques, mask, Wv, Wk, Wq, gk, bk, gq, bq);

    dim3 grid(LQ / 128, NB);
    attn_kernel<<<grid, 128>>>(ques, go, bo, out);
}

// round 11
// speedup vs baseline: 1.6063x; 1.0222x over previous
#include <cuda_runtime.h>
#include <cstdint>

// Problem constants
#define NB   32
#define LQ   2048
#define LK   2048
#define DIN  32
#define DKQ  20
#define EPS  1e-5f
// fold 1/sqrt(20) * log2(e) into q so scores are in log2 domain
#define QSCALE 0.32258572299984063f   // log2(e)/sqrt(20)
#define BIAS_MASKED (-60000.0f)       // f16-finite; ex2 -> exactly 0

// f16 storage strides (in u32 words = f16 pairs)
#define KW 20   // K row: feats 0..19, bias@20, zero-pad to 40 f16 -> 80B
#define VW 20   // V row: dims 0..31, ones-col@32, zero-pad to 40 f16 -> 80B
#define QW 16   // Q row: feats 0..19, 1.0@20, zero-pad to 32 f16 -> 64B

typedef unsigned int u32;

// Scratch (allocation-free rule: __device__ globals), f16 pairs as u32
__device__ u32 d_kb[(size_t)NB * LK * KW];
__device__ u32 d_vb[(size_t)NB * LK * VW];
__device__ u32 d_qb[(size_t)NB * LQ * QW];

// pack two f32 -> f16x2 (lo = first arg)
__device__ __forceinline__ u32 pack_f16(float lo, float hi) {
    u32 d; asm("cvt.rn.f16x2.f32 %0, %1, %2;" : "=r"(d) : "f"(hi), "f"(lo));
    return d;
}
// dual exp2 on packed f16x2
__device__ __forceinline__ u32 ex2h2(u32 a) {
    u32 d; asm("ex2.approx.f16x2 %0, %1;" : "=r"(d) : "r"(a));
    return d;
}
// m16n8k16 f16 mma: D = A*B + C (fp32 accum)
__device__ __forceinline__ void mma_f16(
    float& d0, float& d1, float& d2, float& d3,
    u32 a0, u32 a1, u32 a2, u32 a3, u32 b0, u32 b1,
    float c0, float c1, float c2, float c3)
{
    asm("mma.sync.aligned.m16n8k16.row.col.f32.f16.f16.f32 "
        "{%0,%1,%2,%3},{%4,%5,%6,%7},{%8,%9},{%10,%11,%12,%13};"
        : "=f"(d0), "=f"(d1), "=f"(d2), "=f"(d3)
        : "r"(a0), "r"(a1), "r"(a2), "r"(a3), "r"(b0), "r"(b1),
          "f"(c0), "f"(c1), "f"(c2), "f"(c3));
}
__device__ __forceinline__ void cp16(u32 dst, const void* src) {
    asm volatile("cp.async.cg.shared.global [%0], [%1], 16;" :: "r"(dst), "l"(src));
}
#define CP_COMMIT() asm volatile("cp.async.commit_group;")
#define CP_WAIT0()  asm volatile("cp.async.wait_group 0;")

// ---------------------------------------------------------------------------
// Kernel 1: projections -> f16, split 3 ways by blockIdx.y (0=V, 1=K, 2=Q).
// K rows carry the mask bias at feature 20 (Q has 1.0 there).
// V rows carry a ones-column at dim 32 (softmax denominator via tensor pipe).
// ---------------------------------------------------------------------------
__global__ __launch_bounds__(256) void proj_kernel(
    const float* __restrict__ vals, const float* __restrict__ keys,
    const float* __restrict__ ques, const void* __restrict__ mask_raw,
    const float* __restrict__ Wv, const float* __restrict__ Wk, const float* __restrict__ Wq,
    const float* __restrict__ gk, const float* __restrict__ bk,
    const float* __restrict__ gq, const float* __restrict__ bq)
{
    __shared__ float sW[DIN * DIN];
    __shared__ float sg[DKQ], sb[DKQ];
    __shared__ int s_is_byte;

    int tid  = threadIdx.x;
    int task = blockIdx.y;
    size_t r = (size_t)blockIdx.x * 256 + tid;

    if (task == 0) {
        for (int i = tid; i < DIN * DIN; i += 256) sW[i] = Wv[i];
        __syncthreads();

        float x[DIN];
        const float4* p4 = (const float4*)(vals + r * DIN);
        #pragma unroll
        for (int i = 0; i < 8; i++) {
            float4 t = p4[i];
            x[4*i] = t.x; x[4*i+1] = t.y; x[4*i+2] = t.z; x[4*i+3] = t.w;
        }
        float outr[DIN];
        #pragma unroll
        for (int o = 0; o < DIN; o++) {
            float acc = 0.f;
            #pragma unroll
            for (int d = 0; d < DIN; d++) acc += x[d] * sW[o * DIN + d];
            outr[o] = acc;
        }
        u32 wv[VW];
        #pragma unroll
        for (int p = 0; p < 16; p++) wv[p] = pack_f16(outr[2*p], outr[2*p+1]);
        wv[16] = pack_f16(1.0f, 0.f);      // ones-column @ dim 32
        #pragma unroll
        for (int p = 17; p < VW; p++) wv[p] = 0u;
        uint4* o4 = (uint4*)(d_vb + r * VW);
        #pragma unroll
        for (int i = 0; i < 5; i++)
            o4[i] = make_uint4(wv[4*i], wv[4*i+1], wv[4*i+2], wv[4*i+3]);
    } else {
        const float* W  = (task == 1) ? Wk : Wq;
        const float* gg = (task == 1) ? gk : gq;
        const float* bb = (task == 1) ? bk : bq;
        const float* in = (task == 1) ? keys : ques;
        for (int i = tid; i < DKQ * DIN; i += 256) sW[i] = W[i];
        if (tid < DKQ) { sg[tid] = gg[tid]; sb[tid] = bb[tid]; }
        if (task == 1 && tid == 0) {
            // Detect mask storage: numpy bool (1 byte) vs int32 coercion.
            const unsigned int* wd = (const unsigned int*)mask_raw;
            unsigned int acc = 0;
            for (int k = 0; k < 64; k++) acc |= wd[k] & 0xFFFFFF00u;
            s_is_byte = (acc != 0u);
        }
        __syncthreads();

        float x[DIN];
        const float4* p4 = (const float4*)(in + r * DIN);
        #pragma unroll
        for (int i = 0; i < 8; i++) {
            float4 t = p4[i];
            x[4*i] = t.x; x[4*i+1] = t.y; x[4*i+2] = t.z; x[4*i+3] = t.w;
        }
        float y[DKQ];
        #pragma unroll
        for (int o = 0; o < DKQ; o++) {
            float acc = 0.f;
            #pragma unroll
            for (int d = 0; d < DIN; d++) acc += x[d] * sW[o * DIN + d];
            y[o] = acc;
        }
        float m = 0.f;
        #pragma unroll
        for (int c = 0; c < DKQ; c++) m += y[c];
        m *= (1.f / DKQ);
        float v = 0.f;
        #pragma unroll
        for (int c = 0; c < DKQ; c++) { float d = y[c] - m; v += d * d; }
        v *= (1.f / DKQ);
        float rs = rsqrtf(v + EPS);

        if (task == 1) {
            #pragma unroll
            for (int c = 0; c < DKQ; c++) y[c] = (y[c] - m) * rs * sg[c] + sb[c];
            int mv = s_is_byte ? (int)((const unsigned char*)mask_raw)[r]
                               : ((const int*)mask_raw)[r];
            float bias = mv ? BIAS_MASKED : 0.f;   // True masks OUT
            u32 wv[KW];
            #pragma unroll
            for (int p = 0; p < 10; p++) wv[p] = pack_f16(y[2*p], y[2*p+1]);
            wv[10] = pack_f16(bias, 0.f);
            #pragma unroll
            for (int p = 11; p < KW; p++) wv[p] = 0u;
            uint4* o4 = (uint4*)(d_kb + r * KW);
            #pragma unroll
            for (int i = 0; i < 5; i++)
                o4[i] = make_uint4(wv[4*i], wv[4*i+1], wv[4*i+2], wv[4*i+3]);
        } else {
            #pragma unroll
            for (int c = 0; c < DKQ; c++)
                y[c] = ((y[c] - m) * rs * sg[c] + sb[c]) * QSCALE;
            u32 wv[QW];
            #pragma unroll
            for (int p = 0; p < 10; p++) wv[p] = pack_f16(y[2*p], y[2*p+1]);
            wv[10] = pack_f16(1.0f, 0.f);
            #pragma unroll
            for (int p = 11; p < QW; p++) wv[p] = 0u;
            uint4* o4 = (uint4*)(d_qb + r * QW);
            #pragma unroll
            for (int i = 0; i < 4; i++)
                o4[i] = make_uint4(wv[4*i], wv[4*i+1], wv[4*i+2], wv[4*i+3]);
        }
    }
}

// ---------------------------------------------------------------------------
// Kernel 2: flash attention, f16 m16n8k16 mma + ldmatrix, cp.async
// double-buffered TS=64 tiles. ONE m16 tile (16 queries) per warp:
// CTA = 128 thr = 4 warps = 64 queries; grid = (LQ/64, NB) = 1024 CTAs
// -> ~7 CTAs/SM resident (was 3.5), latency chains fully covered.
// exp via ex2.approx.f16x2; denominator via V ones-column.
// ---------------------------------------------------------------------------
#define TS 64
#define NT (LK / TS)
#define T16 (TS * KW / 4)   // 320 uint4 per tile (K and V identical)

__global__ __launch_bounds__(128) void attn_kernel(
    const float* __restrict__ ques,
    const float* __restrict__ go, const float* __restrict__ bo,
    float* __restrict__ out)
{
    __shared__ u32 sK[2][TS * KW];   // 2 x 5120 B
    __shared__ u32 sV[2][TS * VW];   // 2 x 5120 B

    int tid  = threadIdx.x;
    int w    = tid >> 5;
    int lane = tid & 31;
    int g    = lane >> 2;   // group id (0..7)
    int i    = lane & 3;    // thread in group (0..3)
    int b    = blockIdx.y;
    int qbase = blockIdx.x * 64 + w * 16;

    // ---- Q fragments: one m16 tile x two k16 chunks, in registers ----
    u32 aq[2][4];
    {
        const u32* q0p = d_qb + ((size_t)b * LQ + qbase + g) * QW;
        const u32* q1p = q0p + 8 * QW;
        #pragma unroll
        for (int c = 0; c < 2; c++) {
            aq[c][0] = q0p[8 * c + i];
            aq[c][1] = q1p[8 * c + i];
            aq[c][2] = q0p[8 * c + i + 4];
            aq[c][3] = q1p[8 * c + i + 4];
        }
    }

    // o[nt] nt=0..3: output dims; nt=4: ones-column (denominator)
    float o[5][4];
    #pragma unroll
    for (int nt = 0; nt < 5; nt++)
        #pragma unroll
        for (int r = 0; r < 4; r++) o[nt][r] = 0.f;

    const u32* kgl = d_kb + (size_t)b * LK * KW;
    const u32* vgl = d_vb + (size_t)b * LK * VW;

    u32 sK_u[2], sV_u[2];
    sK_u[0] = (u32)__cvta_generic_to_shared(&sK[0][0]);
    sK_u[1] = (u32)__cvta_generic_to_shared(&sK[1][0]);
    sV_u[0] = (u32)__cvta_generic_to_shared(&sV[0][0]);
    sV_u[1] = (u32)__cvta_generic_to_shared(&sV[1][0]);

    // ---- preamble: async load tile 0 ----
    {
        #pragma unroll
        for (int rr = 0; rr < 3; rr++) {
            int idx = tid + rr * 128;
            if (idx < T16) {
                cp16(sK_u[0] + idx * 16, kgl + idx * 4);
                cp16(sV_u[0] + idx * 16, vgl + idx * 4);
            }
        }
        CP_COMMIT();
    }

    for (int t0 = 0; t0 < NT; t0++) {
        int cur = t0 & 1;
        CP_WAIT0();
        __syncthreads();   // tile t0 ready; all warps done with buffer we refill

        // prefetch tile t0+1 (overlaps with compute below)
        if (t0 + 1 < NT) {
            int nxt = cur ^ 1;
            const u32* kg2 = kgl + (size_t)(t0 + 1) * TS * KW;
            const u32* vg2 = vgl + (size_t)(t0 + 1) * TS * VW;
            #pragma unroll
            for (int rr = 0; rr < 3; rr++) {
                int idx = tid + rr * 128;
                if (idx < T16) {
                    cp16(sK_u[nxt] + idx * 16, kg2 + idx * 4);
                    cp16(sV_u[nxt] + idx * 16, vg2 + idx * 4);
                }
            }
            CP_COMMIT();
        }

        #pragma unroll
        for (int kg = 0; kg < TS / 16; kg++) {
            // ---- K fragments: 8-key groups A (keys kg*16+0..7) and B (+8..15)
            const u32* kA = &sK[cur][(kg * 16 + g) * KW];
            const u32* kB = kA + 8 * KW;
            u32 kbA[4], kbB[4];
            kbA[0] = kA[i];     kbA[1] = kA[i + 4];
            kbA[2] = kA[8 + i]; kbA[3] = kA[12 + i];
            kbB[0] = kB[i];     kbB[1] = kB[i + 4];
            kbB[2] = kB[8 + i]; kbB[3] = kB[12 + i];

            // ---- V fragments: ldmatrix x4 (dims 0..31) + x2 (ones col 32..39)
            u32 vb0[4], vb1[4], vb40, vb41;
            {
                int rrow = lane & 7, mm = lane >> 3;
                u32 a1 = sV_u[cur] + ((kg * 16 + rrow) * VW + mm * 4) * 4;
                u32 a2 = a1 + 8 * VW * 4;
                asm volatile("ldmatrix.sync.aligned.m8n8.x4.trans.shared.b16 "
                             "{%0,%1,%2,%3}, [%4];"
                    : "=r"(vb0[0]), "=r"(vb0[1]), "=r"(vb0[2]), "=r"(vb0[3]) : "r"(a1));
                asm volatile("ldmatrix.sync.aligned.m8n8.x4.trans.shared.b16 "
                             "{%0,%1,%2,%3}, [%4];"
                    : "=r"(vb1[0]), "=r"(vb1[1]), "=r"(vb1[2]), "=r"(vb1[3]) : "r"(a2));
                u32 a3 = sV_u[cur] +
                    ((kg * 16 + (lane & 7) + ((lane >> 3) & 1) * 8) * VW + 16) * 4;
                asm volatile("ldmatrix.sync.aligned.m8n8.x2.trans.shared.b16 "
                             "{%0,%1}, [%2];"
                    : "=r"(vb40), "=r"(vb41) : "r"(a3));
            }

            // QK^T for both 8-key groups (bias included via K[20])
            float sA0 = 0.f, sA1 = 0.f, sA2 = 0.f, sA3 = 0.f;
            float sB0 = 0.f, sB1 = 0.f, sB2 = 0.f, sB3 = 0.f;
            mma_f16(sA0, sA1, sA2, sA3,
                    aq[0][0], aq[0][1], aq[0][2], aq[0][3],
                    kbA[0], kbA[1], sA0, sA1, sA2, sA3);
            mma_f16(sA0, sA1, sA2, sA3,
                    aq[1][0], aq[1][1], aq[1][2], aq[1][3],
                    kbA[2], kbA[3], sA0, sA1, sA2, sA3);
            mma_f16(sB0, sB1, sB2, sB3,
                    aq[0][0], aq[0][1], aq[0][2], aq[0][3],
                    kbB[0], kbB[1], sB0, sB1, sB2, sB3);
            mma_f16(sB0, sB1, sB2, sB3,
                    aq[1][0], aq[1][1], aq[1][2], aq[1][3],
                    kbB[2], kbB[3], sB0, sB1, sB2, sB3);

            // pack score pairs -> f16x2, dual-exp via one MUFU op each.
            // Resulting f16x2 IS the P A-fragment (no further packing).
            u32 pa0 = ex2h2(pack_f16(sA0, sA1));   // row g,   keys 2i,2i+1
            u32 pa1 = ex2h2(pack_f16(sA2, sA3));   // row g+8
            u32 pa2 = ex2h2(pack_f16(sB0, sB1));   // row g,   keys 8+2i..
            u32 pa3 = ex2h2(pack_f16(sB2, sB3));   // row g+8

            #pragma unroll
            for (int nt = 0; nt < 4; nt++) {
                mma_f16(o[nt][0], o[nt][1], o[nt][2], o[nt][3],
                        pa0, pa1, pa2, pa3, vb0[nt], vb1[nt],
                        o[nt][0], o[nt][1], o[nt][2], o[nt][3]);
            }
            // ones-column: accumulates softmax denominator per row
            mma_f16(o[4][0], o[4][1], o[4][2], o[4][3],
                    pa0, pa1, pa2, pa3, vb40, vb41,
                    o[4][0], o[4][1], o[4][2], o[4][3]);
        }
    }

    // ---- epilogue: broadcast l (ones-col, i==0 lanes), normalize, residual,
    //      LayerNorm, store ----
    {
        // l lives at col 32 -> local col 0 -> lanes with i==0
        float l0 = __shfl_sync(0xFFFFFFFFu, o[4][0], lane & 28);  // row g
        float l1 = __shfl_sync(0xFFFFFFFFu, o[4][2], lane & 28);  // row g+8
        float inv0 = 1.f / l0;
        float inv1 = 1.f / l1;

        #pragma unroll
        for (int half = 0; half < 2; half++) {
            int   row  = qbase + g + half * 8;
            float invl = half == 0 ? inv0 : inv1;
            int   r0   = half == 0 ? 0 : 2;

            const float2* qr = (const float2*)(ques + ((size_t)b * LQ + row) * DIN);
            float x[4][2];
            float ssum = 0.f;
            #pragma unroll
            for (int nt = 0; nt < 4; nt++) {
                float2 qv = qr[nt * 4 + i];
                x[nt][0] = o[nt][r0]     * invl + qv.x;
                x[nt][1] = o[nt][r0 + 1] * invl + qv.y;
                ssum += x[nt][0] + x[nt][1];
            }
            ssum += __shfl_xor_sync(0xFFFFFFFFu, ssum, 1);
            ssum += __shfl_xor_sync(0xFFFFFFFFu, ssum, 2);
            float m = ssum * (1.f / DIN);
            float v = 0.f;
            #pragma unroll
            for (int nt = 0; nt < 4; nt++) {
                float d0 = x[nt][0] - m, d1 = x[nt][1] - m;
                v += d0 * d0 + d1 * d1;
            }
            v += __shfl_xor_sync(0xFFFFFFFFu, v, 1);
            v += __shfl_xor_sync(0xFFFFFFFFu, v, 2);
            float rs = rsqrtf(v * (1.f / DIN) + EPS);

            float2* po = (float2*)(out + ((size_t)b * LQ + row) * DIN);
            #pragma unroll
            for (int nt = 0; nt < 4; nt++) {
                int col = nt * 8 + 2 * i;
                float2 tt;
                tt.x = (x[nt][0] - m) * rs * __ldg(go + col)     + __ldg(bo + col);
                tt.y = (x[nt][1] - m) * rs * __ldg(go + col + 1) + __ldg(bo + col + 1);
                po[nt * 4 + i] = tt;
            }
        }
    }
}

// ---------------------------------------------------------------------------
extern "C" void kernel_launch(void* const* d_in, const int* in_sizes, int n_in,
                              void* d_out, int out_size)
{
    const float* vals = (const float*)d_in[0];
    const float* keys = (const float*)d_in[1];
    const float* ques = (const float*)d_in[2];
    const void*  mask = d_in[3];
    const float* Wv   = (const float*)d_in[4];
    const float* Wk   = (const float*)d_in[5];
    const float* Wq   = (const float*)d_in[6];
    const float* gk   = (const float*)d_in[7];
    const float* bk   = (const float*)d_in[8];
    const float* gq   = (const float*)d_in[9];
    const float* bq   = (const float*)d_in[10];
    const float* go   = (const float*)d_in[11];
    const float* bo   = (const float*)d_in[12];
    float* out = (float*)d_out;

    dim3 pgrid((NB * LK) / 256, 3);
    proj_kernel<<<pgrid, 256>>>(vals, keys, ques, mask, Wv, Wk, Wq, gk, bk, gq, bq);

    dim3 grid(LQ / 64, NB);
    attn_kernel<<<grid, 128>>>(ques, go, bo, out);
}